// round 2
// baseline (speedup 1.0000x reference)
#include <cuda_runtime.h>
#include <cstddef>

#define NN 100000
#define NE 1600000

// Scratch (allocation-free rule: __device__ globals)
__device__ float g_acc[(size_t)NN * 128];   // segment sums  [N,128]
__device__ float g_cnt[NN];                 // segment counts
__device__ float g_mid[(size_t)NN * 256];   // node MLP hidden [N,256]
__device__ int   g_is64;                    // edge_index dtype flag

// ---------------------------------------------------------------------------
// helpers
// ---------------------------------------------------------------------------
template <int N4>
__device__ __forceinline__ void fma_row(float* acc, float a, const float* wrow)
{
    const float4* w = reinterpret_cast<const float4*>(wrow);
#pragma unroll
    for (int j = 0; j < N4; j++) {
        float4 wv = w[j];
        acc[4 * j + 0] = fmaf(a, wv.x, acc[4 * j + 0]);
        acc[4 * j + 1] = fmaf(a, wv.y, acc[4 * j + 1]);
        acc[4 * j + 2] = fmaf(a, wv.z, acc[4 * j + 2]);
        acc[4 * j + 3] = fmaf(a, wv.w, acc[4 * j + 3]);
    }
}

// ---------------------------------------------------------------------------
// K-1: detect edge_index dtype (int64 vs int32).
// If the buffer really holds int64 indices, the first 128 int64 values are all
// in [0, NN). If it holds int32, each int64 read packs two random indices and
// is >= 2^32 with overwhelming probability.
// ---------------------------------------------------------------------------
__global__ void detect_kernel(const long long* __restrict__ ei)
{
    if (threadIdx.x == 0 && blockIdx.x == 0) {
        int ok = 1;
        for (int i = 0; i < 128; i++) {
            long long v = ei[i];
            if (v < 0 || v >= NN) { ok = 0; break; }
        }
        g_is64 = ok;
    }
}

// ---------------------------------------------------------------------------
// K0: zero accumulators
// ---------------------------------------------------------------------------
__global__ void zero_kernel()
{
    size_t i = (size_t)blockIdx.x * blockDim.x + threadIdx.x;
    size_t stride = (size_t)gridDim.x * blockDim.x;
    for (size_t k = i; k < (size_t)NN * 128; k += stride) g_acc[k] = 0.0f;
    for (size_t k = i; k < (size_t)NN; k += stride) g_cnt[k] = 0.0f;
}

// ---------------------------------------------------------------------------
// K1: edge MLP + scatter-add
//   h1 = relu([x[src], e] @ W1 + b1)   (43 -> 64)
//   h2 = relu(h1 @ W2 + b2)            (64 -> 128)
//   g_acc[dst] += h2 ; g_cnt[dst] += 1
// ---------------------------------------------------------------------------
__global__ __launch_bounds__(128)
void edge_kernel(const float* __restrict__ x,
                 const void* __restrict__ ei_raw,
                 const float* __restrict__ ea,
                 const float* __restrict__ W1, const float* __restrict__ b1,
                 const float* __restrict__ W2, const float* __restrict__ b2)
{
    __shared__ float sW1[43 * 64];   // 11 KB
    __shared__ float sb1[64];
    __shared__ float sW2[64 * 128];  // 32 KB
    __shared__ float sb2[128];

    const int tid = threadIdx.x;
    for (int i = tid; i < 43 * 64; i += 128) sW1[i] = W1[i];
    if (tid < 64) sb1[tid] = b1[tid];
    for (int i = tid; i < 64 * 128; i += 128) sW2[i] = W2[i];
    if (tid < 128) sb2[tid] = b2[tid];
    __syncthreads();

    const int e = blockIdx.x * 128 + tid;
    if (e >= NE) return;

    int dst, src;
    if (g_is64) {
        const long long* ei = (const long long*)ei_raw;
        dst = (int)ei[e];          // edge_index[0] : destination (scatter key)
        src = (int)ei[NE + e];     // edge_index[1] : source (gather key)
    } else {
        const int* ei = (const int*)ei_raw;
        dst = ei[e];
        src = ei[NE + e];
    }
    // defensive clamp (never triggers on valid data; prevents UB on surprises)
    dst = min(max(dst, 0), NN - 1);
    src = min(max(src, 0), NN - 1);

    float h1[64];
#pragma unroll
    for (int j = 0; j < 64; j++) h1[j] = sb1[j];

    // x[src] part (rows 0..3 of W1)
    {
        const float4 xv = *reinterpret_cast<const float4*>(x + (size_t)src * 4);
        const float xa[4] = {xv.x, xv.y, xv.z, xv.w};
#pragma unroll
        for (int k = 0; k < 4; k++)
            fma_row<16>(h1, xa[k], sW1 + k * 64);
    }
    // edge_attr part (rows 4..42 of W1)
    {
        const float* ep = ea + (size_t)e * 39;
#pragma unroll
        for (int k = 0; k < 39; k++) {
            const float a = __ldg(ep + k);
            fma_row<16>(h1, a, sW1 + (4 + k) * 64);
        }
    }
#pragma unroll
    for (int j = 0; j < 64; j++) h1[j] = fmaxf(h1[j], 0.0f);

    // Second layer, 4 output chunks of 32, then 128-bit atomic scatter
    float* accb = g_acc + (size_t)dst * 128;
#pragma unroll 1
    for (int jc = 0; jc < 4; jc++) {
        float acc[32];
#pragma unroll
        for (int j = 0; j < 32; j++) acc[j] = sb2[jc * 32 + j];
#pragma unroll
        for (int k = 0; k < 64; k++)
            fma_row<8>(acc, h1[k], sW2 + k * 128 + jc * 32);

#pragma unroll
        for (int j = 0; j < 8; j++) {
            float4 v = make_float4(fmaxf(acc[4 * j + 0], 0.0f),
                                   fmaxf(acc[4 * j + 1], 0.0f),
                                   fmaxf(acc[4 * j + 2], 0.0f),
                                   fmaxf(acc[4 * j + 3], 0.0f));
            atomicAdd(reinterpret_cast<float4*>(accb + jc * 32 + 4 * j), v);
        }
    }
    atomicAdd(&g_cnt[dst], 1.0f);
}

// ---------------------------------------------------------------------------
// K2: node MLP layer 1 (fused mean + concat):
//   in2 = [x[n], g_acc[n]/max(cnt,1)]  (132)
//   g_mid[n] = relu(in2 @ W3 + b3)     (132 -> 256)
// ---------------------------------------------------------------------------
__global__ __launch_bounds__(128)
void node1_kernel(const float* __restrict__ x,
                  const float* __restrict__ W3, const float* __restrict__ b3)
{
    __shared__ float sW[132 * 64];   // 33.8 KB (one 64-wide output chunk)
    __shared__ float sb[64];

    const int tid = threadIdx.x;
    const int node = blockIdx.x * 128 + tid;
    const bool valid = node < NN;
    const int nd = valid ? node : NN - 1;

    const float inv = 1.0f / fmaxf(g_cnt[nd], 1.0f);
    const float4 xv = *reinterpret_cast<const float4*>(x + (size_t)nd * 4);
    const float xa[4] = {xv.x, xv.y, xv.z, xv.w};

#pragma unroll 1
    for (int jc = 0; jc < 4; jc++) {
        __syncthreads();   // protect previous chunk's sW reads
        for (int i = tid; i < 132 * 64; i += 128) {
            int k = i >> 6, j = i & 63;
            sW[i] = W3[k * 256 + jc * 64 + j];
        }
        if (tid < 64) sb[tid] = b3[jc * 64 + tid];
        __syncthreads();

        float acc[64];
#pragma unroll
        for (int j = 0; j < 64; j++) acc[j] = sb[j];

#pragma unroll
        for (int k = 0; k < 4; k++)
            fma_row<16>(acc, xa[k], sW + k * 64);

#pragma unroll 1
        for (int kc = 0; kc < 4; kc++) {
            float a32[32];
            const float4* ap =
                reinterpret_cast<const float4*>(g_acc + (size_t)nd * 128 + kc * 32);
#pragma unroll
            for (int i = 0; i < 8; i++) {
                float4 v = __ldg(ap + i);
                a32[4 * i + 0] = v.x * inv;
                a32[4 * i + 1] = v.y * inv;
                a32[4 * i + 2] = v.z * inv;
                a32[4 * i + 3] = v.w * inv;
            }
#pragma unroll
            for (int k = 0; k < 32; k++)
                fma_row<16>(acc, a32[k], sW + (4 + kc * 32 + k) * 64);
        }

        if (valid) {
            float4* op = reinterpret_cast<float4*>(g_mid + (size_t)node * 256 + jc * 64);
#pragma unroll
            for (int j = 0; j < 16; j++) {
                op[j] = make_float4(fmaxf(acc[4 * j + 0], 0.0f),
                                    fmaxf(acc[4 * j + 1], 0.0f),
                                    fmaxf(acc[4 * j + 2], 0.0f),
                                    fmaxf(acc[4 * j + 3], 0.0f));
            }
        }
    }
}

// ---------------------------------------------------------------------------
// K3: node MLP layer 2:  out = relu(g_mid @ W4 + b4)   (256 -> 256)
// Dynamic shared: 64 KB W4 chunk + 64 floats bias
// ---------------------------------------------------------------------------
__global__ __launch_bounds__(128)
void node2_kernel(const float* __restrict__ W4, const float* __restrict__ b4,
                  float* __restrict__ out)
{
    extern __shared__ float smem[];
    float* sW = smem;             // 256*64
    float* sb = smem + 256 * 64;  // 64

    const int tid = threadIdx.x;
    const int node = blockIdx.x * 128 + tid;
    const bool valid = node < NN;
    const int nd = valid ? node : NN - 1;

#pragma unroll 1
    for (int jc = 0; jc < 4; jc++) {
        __syncthreads();
        for (int i = tid; i < 256 * 64; i += 128) {
            int k = i >> 6, j = i & 63;
            sW[i] = W4[k * 256 + jc * 64 + j];
        }
        if (tid < 64) sb[tid] = b4[jc * 64 + tid];
        __syncthreads();

        float acc[64];
#pragma unroll
        for (int j = 0; j < 64; j++) acc[j] = sb[j];

#pragma unroll 1
        for (int kc = 0; kc < 8; kc++) {
            float a32[32];
            const float4* ap =
                reinterpret_cast<const float4*>(g_mid + (size_t)nd * 256 + kc * 32);
#pragma unroll
            for (int i = 0; i < 8; i++) {
                float4 v = __ldg(ap + i);
                a32[4 * i + 0] = v.x;
                a32[4 * i + 1] = v.y;
                a32[4 * i + 2] = v.z;
                a32[4 * i + 3] = v.w;
            }
#pragma unroll
            for (int k = 0; k < 32; k++)
                fma_row<16>(acc, a32[k], sW + (kc * 32 + k) * 64);
        }

        if (valid) {
            float4* op = reinterpret_cast<float4*>(out + (size_t)node * 256 + jc * 64);
#pragma unroll
            for (int j = 0; j < 16; j++) {
                op[j] = make_float4(fmaxf(acc[4 * j + 0], 0.0f),
                                    fmaxf(acc[4 * j + 1], 0.0f),
                                    fmaxf(acc[4 * j + 2], 0.0f),
                                    fmaxf(acc[4 * j + 3], 0.0f));
            }
        }
    }
}

// ---------------------------------------------------------------------------
// launch
// ---------------------------------------------------------------------------
extern "C" void kernel_launch(void* const* d_in, const int* in_sizes, int n_in,
                              void* d_out, int out_size)
{
    const float*     x  = (const float*)d_in[0];
    const void*      ei = d_in[1];
    const float*     ea = (const float*)d_in[2];
    const float*     W1 = (const float*)d_in[3];
    const float*     b1 = (const float*)d_in[4];
    const float*     W2 = (const float*)d_in[5];
    const float*     b2 = (const float*)d_in[6];
    const float*     W3 = (const float*)d_in[7];
    const float*     b3 = (const float*)d_in[8];
    const float*     W4 = (const float*)d_in[9];
    const float*     b4 = (const float*)d_in[10];
    float* out = (float*)d_out;

    static const int node2_smem = 256 * 64 * 4 + 64 * 4;
    cudaFuncSetAttribute(node2_kernel,
                         cudaFuncAttributeMaxDynamicSharedMemorySize, node2_smem);

    detect_kernel<<<1, 32>>>((const long long*)ei);
    zero_kernel<<<2048, 256>>>();
    edge_kernel<<<(NE + 127) / 128, 128>>>(x, ei, ea, W1, b1, W2, b2);
    node1_kernel<<<(NN + 127) / 128, 128>>>(x, W3, b3);
    node2_kernel<<<(NN + 127) / 128, 128, node2_smem>>>(W4, b4, out);
}